// round 1
// baseline (speedup 1.0000x reference)
#include <cuda_runtime.h>
#include <cuda_bf16.h>
#include <stdint.h>

// RoIAlign: feat (B=4, C=256, H=200, W=304) fp32, rois (N,5) fp32
// OUT=7, SCALE=0.25, sampling_ratio=1, aligned=False
// out: (N, C, 7, 7) fp32

#define B_ 4
#define C_ 256
#define H_ 200
#define W_ 304
#define OUT_ 7
#define BINS_PER_ROI (OUT_ * OUT_)      // 49
#define HW_ (H_ * W_)                   // 60800
#define CHW_ (C_ * HW_)                 // 15,564,800
#define SCALE_ 0.25f

#define MAX_ROIS 8192
// Per-bin precomputed data (SoA, L2-resident: ~2 MB for 2000 rois)
__device__ int    g_off[MAX_ROIS * BINS_PER_ROI];   // b*CHW + y0*W + x0
__device__ float4 g_w[MAX_ROIS * BINS_PER_ROI];     // bilinear weights * valid

// ---------------------------------------------------------------------------
// Phase 1: one thread per (roi, bin). Computes sample point, clamps,
// re-parameterizes edge clamps so the +1 taps are always in-bounds,
// folds the validity mask into the weights.
// ---------------------------------------------------------------------------
__global__ __launch_bounds__(256)
void roi_prep_kernel(const float* __restrict__ rois, int n_bins) {
    int i = blockIdx.x * blockDim.x + threadIdx.x;
    if (i >= n_bins) return;

    int n  = i / BINS_PER_ROI;
    int p  = i - n * BINS_PER_ROI;
    int ph = p / OUT_;
    int pw = p - ph * OUT_;

    const float* r = rois + n * 5;
    int   b   = (int)r[0];
    float sx1 = r[1] * SCALE_;
    float sy1 = r[2] * SCALE_;
    float sx2 = r[3] * SCALE_;
    float sy2 = r[4] * SCALE_;

    float rw = fmaxf(sx2 - sx1, 1.0f);   // aligned=False -> clamp to 1
    float rh = fmaxf(sy2 - sy1, 1.0f);
    float bin_w = rw * (1.0f / OUT_);
    float bin_h = rh * (1.0f / OUT_);

    // sampling_ratio = 1: single sample at bin center (grid = idx + 0.5)
    float x = sx1 + ((float)pw + 0.5f) * bin_w;
    float y = sy1 + ((float)ph + 0.5f) * bin_h;

    float valid = (y > -1.0f && y < (float)H_ && x > -1.0f && x < (float)W_)
                      ? 1.0f : 0.0f;

    y = fminf(fmaxf(y, 0.0f), (float)(H_ - 1));
    x = fminf(fmaxf(x, 0.0f), (float)(W_ - 1));

    int   y0 = (int)floorf(y);
    int   x0 = (int)floorf(x);
    float ly = y - (float)y0;
    float lx = x - (float)x0;

    // Edge re-parameterization: keep (y0+1, x0+1) taps in-bounds.
    // At y==H-1: ly was 0 -> represent as y0=H-2, ly=1 (identical value).
    if (y0 >= H_ - 1) { y0 = H_ - 2; ly = 1.0f; }
    if (x0 >= W_ - 1) { x0 = W_ - 2; lx = 1.0f; }

    float hy = 1.0f - ly;
    float hx = 1.0f - lx;

    g_off[i] = b * CHW_ + y0 * W_ + x0;
    g_w[i]   = make_float4(hy * hx * valid,
                           hy * lx * valid,
                           ly * hx * valid,
                           ly * lx * valid);
}

// ---------------------------------------------------------------------------
// Phase 2: one thread per output element, idx = ((n*C + c)*49 + p).
// Writes are fully coalesced; bin metadata loads are contiguous and
// L2-cached; 4 feat taps per thread.
// ---------------------------------------------------------------------------
__global__ __launch_bounds__(256)
void roi_gather_kernel(const float* __restrict__ feat,
                       float* __restrict__ out,
                       int total) {
    int idx = blockIdx.x * blockDim.x + threadIdx.x;
    if (idx >= total) return;

    int p   = idx % BINS_PER_ROI;
    int nc  = idx / BINS_PER_ROI;
    int c   = nc % C_;
    int n   = nc / C_;
    int bin = n * BINS_PER_ROI + p;

    int    off = g_off[bin] + c * HW_;
    float4 w   = g_w[bin];

    const float* ptr = feat + off;
    float f00 = __ldg(ptr);
    float f01 = __ldg(ptr + 1);
    float f10 = __ldg(ptr + W_);
    float f11 = __ldg(ptr + W_ + 1);

    out[idx] = f00 * w.x + f01 * w.y + f10 * w.z + f11 * w.w;
}

// ---------------------------------------------------------------------------
extern "C" void kernel_launch(void* const* d_in, const int* in_sizes, int n_in,
                              void* d_out, int out_size) {
    const float* feat = (const float*)d_in[0];
    const float* rois = (const float*)d_in[1];
    float* out = (float*)d_out;

    int N = in_sizes[1] / 5;
    int n_bins = N * BINS_PER_ROI;
    int total  = N * C_ * BINS_PER_ROI;

    roi_prep_kernel<<<(n_bins + 255) / 256, 256>>>(rois, n_bins);
    roi_gather_kernel<<<(total + 255) / 256, 256>>>(feat, out, total);
}

// round 4
// speedup vs baseline: 1.6241x; 1.6241x over previous
#include <cuda_runtime.h>
#include <cuda_bf16.h>
#include <stdint.h>

// RoIAlign: feat (B=4, C=256, H=200, W=304) fp32, rois (N,5) fp32
// OUT=7, SCALE=0.25, sampling_ratio=1, aligned=False
// out: (N, C, 7, 7) fp32

#define B_ 4
#define C_ 256
#define H_ 200
#define W_ 304
#define OUT_ 7
#define BINS_PER_ROI (OUT_ * OUT_)      // 49
#define HW_ (H_ * W_)                   // 60800
#define CHW_ (C_ * HW_)                 // 15,564,800
#define SCALE_ 0.25f

#define CG_ 32                          // channels per gather block
#define NCG_ (C_ / CG_)                 // 8 channel groups
#define ELEMS_PER_BLOCK (CG_ * BINS_PER_ROI)  // 1568

#define MAX_ROIS 8192
__device__ int    g_off[MAX_ROIS * BINS_PER_ROI];   // b*CHW + y0*W + x0
__device__ float4 g_w[MAX_ROIS * BINS_PER_ROI];     // bilinear weights * valid
__device__ int    g_batch[MAX_ROIS];                // batch index per roi
__device__ int    g_order[MAX_ROIS];                // rois sorted by batch

// ---------------------------------------------------------------------------
// Phase 1: one thread per (roi, bin).
// ---------------------------------------------------------------------------
__global__ __launch_bounds__(256)
void roi_prep_kernel(const float* __restrict__ rois, int n_bins) {
    int i = blockIdx.x * blockDim.x + threadIdx.x;
    if (i >= n_bins) return;

    int n  = i / BINS_PER_ROI;
    int p  = i - n * BINS_PER_ROI;
    int ph = p / OUT_;
    int pw = p - ph * OUT_;

    const float* r = rois + n * 5;
    int   b   = (int)r[0];
    float sx1 = r[1] * SCALE_;
    float sy1 = r[2] * SCALE_;
    float sx2 = r[3] * SCALE_;
    float sy2 = r[4] * SCALE_;

    if (p == 0) g_batch[n] = b;

    float rw = fmaxf(sx2 - sx1, 1.0f);   // aligned=False -> clamp to 1
    float rh = fmaxf(sy2 - sy1, 1.0f);
    float bin_w = rw * (1.0f / OUT_);
    float bin_h = rh * (1.0f / OUT_);

    // sampling_ratio = 1: single sample at bin center
    float x = sx1 + ((float)pw + 0.5f) * bin_w;
    float y = sy1 + ((float)ph + 0.5f) * bin_h;

    float valid = (y > -1.0f && y < (float)H_ && x > -1.0f && x < (float)W_)
                      ? 1.0f : 0.0f;

    y = fminf(fmaxf(y, 0.0f), (float)(H_ - 1));
    x = fminf(fmaxf(x, 0.0f), (float)(W_ - 1));

    int   y0 = (int)floorf(y);
    int   x0 = (int)floorf(x);
    float ly = y - (float)y0;
    float lx = x - (float)x0;

    // Edge re-parameterization: keep (y0+1, x0+1) taps in-bounds.
    if (y0 >= H_ - 1) { y0 = H_ - 2; ly = 1.0f; }
    if (x0 >= W_ - 1) { x0 = W_ - 2; lx = 1.0f; }

    float hy = 1.0f - ly;
    float hx = 1.0f - lx;

    g_off[i] = b * CHW_ + y0 * W_ + x0;
    g_w[i]   = make_float4(hy * hx * valid,
                           hy * lx * valid,
                           ly * hx * valid,
                           ly * lx * valid);
}

// ---------------------------------------------------------------------------
// Phase 1b: single-block counting sort of rois by batch index (4 buckets).
// Order within a bucket is irrelevant (each roi writes a disjoint output
// slice), so shared-memory atomic scatter is deterministic-output-safe.
// ---------------------------------------------------------------------------
__global__ __launch_bounds__(256)
void roi_sort_kernel(int n_rois) {
    __shared__ int s_count[B_];
    __shared__ int s_base[B_];
    __shared__ int s_pos[B_];

    int tid = threadIdx.x;
    if (tid < B_) s_count[tid] = 0;
    __syncthreads();

    for (int n = tid; n < n_rois; n += blockDim.x)
        atomicAdd(&s_count[g_batch[n]], 1);
    __syncthreads();

    if (tid == 0) {
        int acc = 0;
        for (int b = 0; b < B_; b++) { s_base[b] = acc; acc += s_count[b]; s_pos[b] = 0; }
    }
    __syncthreads();

    for (int n = tid; n < n_rois; n += blockDim.x) {
        int b = g_batch[n];
        int pos = s_base[b] + atomicAdd(&s_pos[b], 1);
        g_order[pos] = n;
    }
}

// ---------------------------------------------------------------------------
// Phase 2: one block = (batch-sorted roi slot, 32-channel group).
// Bin metadata (49 x 20B) is staged in shared memory once per block,
// removing the 256x-redundant metadata traffic. Blocks are ordered
// slot-major so a concurrent wave stays within one image's features
// (~62 MB < L2), turning cross-roi tap reuse into L2 hits.
// Stores: each block writes a contiguous 1568-float output slice.
// ---------------------------------------------------------------------------
__global__ __launch_bounds__(256)
void roi_gather_kernel(const float* __restrict__ feat,
                       float* __restrict__ out) {
    __shared__ int    s_off[BINS_PER_ROI];
    __shared__ float4 s_w[BINS_PER_ROI];

    int slot = blockIdx.x / NCG_;
    int cg   = blockIdx.x - slot * NCG_;
    int n    = g_order[slot];
    int c0   = cg * CG_;

    int tid = threadIdx.x;
    if (tid < BINS_PER_ROI) {
        int bin = n * BINS_PER_ROI + tid;
        s_off[tid] = g_off[bin];
        s_w[tid]   = g_w[bin];
    }
    __syncthreads();

    float* out_base = out + (n * C_ + c0) * BINS_PER_ROI;

    #pragma unroll
    for (int idx = tid; idx < ELEMS_PER_BLOCK; idx += 256) {
        int c = idx / BINS_PER_ROI;
        int p = idx - c * BINS_PER_ROI;

        int    off = s_off[p] + (c0 + c) * HW_;
        float4 w   = s_w[p];

        const float* ptr = feat + off;
        float f00 = __ldg(ptr);
        float f01 = __ldg(ptr + 1);
        float f10 = __ldg(ptr + W_);
        float f11 = __ldg(ptr + W_ + 1);

        out_base[idx] = f00 * w.x + f01 * w.y + f10 * w.z + f11 * w.w;
    }
}

// ---------------------------------------------------------------------------
extern "C" void kernel_launch(void* const* d_in, const int* in_sizes, int n_in,
                              void* d_out, int out_size) {
    const float* feat = (const float*)d_in[0];
    const float* rois = (const float*)d_in[1];
    float* out = (float*)d_out;

    int N = in_sizes[1] / 5;
    int n_bins = N * BINS_PER_ROI;

    roi_prep_kernel<<<(n_bins + 255) / 256, 256>>>(rois, n_bins);
    roi_sort_kernel<<<1, 256>>>(N);
    roi_gather_kernel<<<N * NCG_, 256>>>(feat, out);
}